// round 16
// baseline (speedup 1.0000x reference)
#include <cuda_runtime.h>
#include <cuda_fp16.h>
#include <cstdint>

#define R_TOT 1152
#define B_TOT 256
#define B_HALF 128
#define C_N 10
#define O_N 16
#define CO 160
#define I_N 8

// kroute tiling
#define NCH_R 16           // route chunks per batch
#define RCHK 72            // rows per route chunk
#define PAD_H 168          // fp16 row stride: 336B rows, 16B-aligned
#define TILE_H (RCHK * PAD_H)          // 12096 halves
#define TILE_BYTES (TILE_H * 2)        // 24192 (16B multiple)

// k1 tiling
#define TB 8               // batches per k1 block
#define K1_RC 36           // rows per k1 block
#define K1_PARTS 32        // s1 partial chunks

// Scratch (device globals: allocation-free kernel_launch)
__device__ __half g_uh[(size_t)B_TOT * NCH_R * TILE_H];      // 49.5MB per half (L2-resident)
__device__ __half2 g_wh[(size_t)R_TOT * 80 * I_N];           // W packed column pairs
__device__ float  g_b2[(size_t)B_TOT * R_TOT * C_N];         // b after iter-1 update
__device__ float  g_spart1[(size_t)K1_PARTS * B_TOT * CO];   // k1 partial s
__device__ float  g_spart2[2][(size_t)NCH_R * B_TOT * CO];   // kroute partial s
__device__ int    g_cnt[B_TOT];                              // last-block counters

__device__ __forceinline__ uint32_t smem_u32(const void* p) {
    uint32_t a;
    asm("{ .reg .u64 t; cvta.to.shared.u64 t, %1; cvt.u32.u64 %0, t; }" : "=r"(a) : "l"(p));
    return a;
}
__device__ __forceinline__ __half2 u2h(uint32_t v) {
    return *reinterpret_cast<__half2*>(&v);
}

// ---------------------------------------------------------------------------
// K0: pack W (fp32 [R, CO, I]) into column-pair half2 layout [r][u][i].
// ---------------------------------------------------------------------------
__global__ __launch_bounds__(256) void k0(const float* __restrict__ W) {
    int idx = blockIdx.x * 256 + threadIdx.x;        // over R_TOT*80*8
    if (idx >= R_TOT * 80 * I_N) return;
    int i = idx & 7;
    int t = idx >> 3;
    int u = t % 80;
    int r = t / 80;
    float w0 = W[((size_t)r * CO + 2 * u) * I_N + i];
    float w1 = W[((size_t)r * CO + 2 * u + 1) * I_N + i];
    g_wh[idx] = __floats2half2_rn(w0, w1);
}

// ---------------------------------------------------------------------------
// K1 (per batch half): u_hat via HFMA2 (2 columns/thread) -> fp16 tiles,
// fused softmax(b_init) + fp32 s1 partials.
// grid = 16 b-tiles x 32 r-chunks = 512 blocks, 160 threads, ~21KB SMEM.
// ---------------------------------------------------------------------------
__global__ __launch_bounds__(160) void k1(const float* __restrict__ x,
                                          const float* __restrict__ binit,
                                          int b_half) {
    const int bt = blockIdx.x & 15;
    const int rc = blockIdx.x >> 4;          // 0..31 (36-row chunk)
    const int b0 = b_half * B_HALF + bt * TB;
    const int tid = threadIdx.x;
    const int r0 = rc * K1_RC;
    const int chk_g = rc >> 1;               // 72-row tile id
    const int rin0 = (rc & 1) * K1_RC;       // row offset within tile

    const int grp = tid / 80;                // batch half (4 batches each)
    const int u   = tid - grp * 80;          // column pair (cols 2u, 2u+1)
    const int c   = u >> 3;                  // capsule (same for both cols)
    const int bb0 = grp * 4;

    __shared__ __half2 x2_sm[TB][K1_RC][I_N];   // 9.2KB
    __shared__ float   c_sm[TB][K1_RC][C_N];    // 11.5KB

    const float4* x4 = reinterpret_cast<const float4*>(x);

    // stage x as duplicated half2
    for (int i = tid; i < TB * K1_RC * 2; i += 160) {
        int bb = i / (K1_RC * 2);
        int rem = i - bb * (K1_RC * 2);
        float4 v = x4[((size_t)(b0 + bb) * R_TOT + r0) * 2 + rem];
        __half2* dst = &x2_sm[bb][0][0] + rem * 4;
        dst[0] = __float2half2_rn(v.x);
        dst[1] = __float2half2_rn(v.y);
        dst[2] = __float2half2_rn(v.z);
        dst[3] = __float2half2_rn(v.w);
    }
    // softmax(b_init)
    for (int p = tid; p < TB * K1_RC; p += 160) {
        int bb = p / K1_RC;
        int rr = p - bb * K1_RC;
        const float* bp = binit + ((size_t)(b0 + bb) * R_TOT + r0 + rr) * C_N;
        float e[C_N];
        float m = bp[0];
#pragma unroll
        for (int j = 1; j < C_N; j++) m = fmaxf(m, bp[j]);
        float sum = 0.f;
#pragma unroll
        for (int j = 0; j < C_N; j++) { e[j] = __expf(bp[j] - m); sum += e[j]; }
        float inv = 1.f / sum;
#pragma unroll
        for (int j = 0; j < C_N; j++) c_sm[bb][rr][j] = e[j] * inv;
    }
    __syncthreads();

    float2 s_acc[4];
#pragma unroll
    for (int i = 0; i < 4; i++) s_acc[i] = make_float2(0.f, 0.f);

    for (int rr = 0; rr < K1_RC; rr++) {
        const int r = r0 + rr;
        const int rin = rin0 + rr;
        __half2 w[8];
        {
            const uint4* wp = reinterpret_cast<const uint4*>(g_wh + ((size_t)r * 80 + u) * I_N);
            uint4 a = wp[0], bq = wp[1];
            w[0] = u2h(a.x);  w[1] = u2h(a.y);  w[2] = u2h(a.z);  w[3] = u2h(a.w);
            w[4] = u2h(bq.x); w[5] = u2h(bq.y); w[6] = u2h(bq.z); w[7] = u2h(bq.w);
        }
#pragma unroll
        for (int bbl = 0; bbl < 4; bbl++) {
            const int bb = bb0 + bbl;
            const uint4* xq = reinterpret_cast<const uint4*>(&x2_sm[bb][rr][0]);
            uint4 xa = xq[0], xb = xq[1];
            __half2 acc = __hmul2(w[0], u2h(xa.x));
            acc = __hfma2(w[1], u2h(xa.y), acc);
            acc = __hfma2(w[2], u2h(xa.z), acc);
            acc = __hfma2(w[3], u2h(xa.w), acc);
            acc = __hfma2(w[4], u2h(xb.x), acc);
            acc = __hfma2(w[5], u2h(xb.y), acc);
            acc = __hfma2(w[6], u2h(xb.z), acc);
            acc = __hfma2(w[7], u2h(xb.w), acc);
            __half2* dst = reinterpret_cast<__half2*>(
                g_uh + ((size_t)(b0 + bb) * NCH_R + chk_g) * TILE_H + (size_t)rin * PAD_H);
            dst[u] = acc;
            float2 f = __half22float2(acc);
            const float cf = c_sm[bb][rr][c];
            s_acc[bbl].x = fmaf(cf, f.x, s_acc[bbl].x);
            s_acc[bbl].y = fmaf(cf, f.y, s_acc[bbl].y);
        }
    }
#pragma unroll
    for (int bbl = 0; bbl < 4; bbl++) {
        float2* sp = reinterpret_cast<float2*>(
            g_spart1 + ((size_t)rc * B_TOT + (b0 + bb0 + bbl)) * CO);
        sp[u] = s_acc[bbl];
    }
}

// ---------------------------------------------------------------------------
// Fused routing pass (iter = 2 or 3) over one batch half.
// Bulk-copy 24.2KB fp16 tile (L2-hot), overlap with v recompute (half2),
// phase A = HFMA2 agreement, phase B = fp32 accumulation.
// Iter 3 last block per batch does final squash. grid = 2048, 160 threads.
// ---------------------------------------------------------------------------
__global__ __launch_bounds__(160) void kroute(const float* __restrict__ binit,
                                              float* __restrict__ out, int iter,
                                              int b_half) {
    extern __shared__ __align__(16) char smem_raw[];
    __half* uh = reinterpret_cast<__half*>(smem_raw);             // TILE_H halves
    float* cT  = reinterpret_cast<float*>(smem_raw + TILE_BYTES); // [C_N][RCHK]
    __half2* vsh = reinterpret_cast<__half2*>(cT + C_N * RCHK);   // 80 half2
    float* sp  = reinterpret_cast<float*>(vsh + 80);              // [2][CO]
    __shared__ __align__(8) unsigned long long mbar;
    __shared__ int is_last;

    const int b   = b_half * B_HALF + (blockIdx.x >> 4);
    const int chk = blockIdx.x & 15;
    const int tid = threadIdx.x;

    const uint32_t uh_s = smem_u32(uh);
    const uint32_t mb_s = smem_u32(&mbar);

    if (tid == 0) {
        asm volatile("mbarrier.init.shared.b64 [%0], 1;" :: "r"(mb_s) : "memory");
        asm volatile("mbarrier.arrive.expect_tx.shared.b64 _, [%0], %1;"
                     :: "r"(mb_s), "r"((uint32_t)TILE_BYTES) : "memory");
        const __half* src = g_uh + ((size_t)b * NCH_R + chk) * TILE_H;
        asm volatile("cp.async.bulk.shared::cta.global.mbarrier::complete_tx::bytes "
                     "[%0], [%1], %2, [%3];"
                     :: "r"(uh_s), "l"(src), "r"((uint32_t)TILE_BYTES), "r"(mb_s)
                     : "memory");
    }

    // Overlap with bulk copy: recompute v = squash(sum of prev partials) as half2.
    if (tid < CO) {
        float s = 0.f;
        if (iter == 2) {
#pragma unroll
            for (int p = 0; p < K1_PARTS; p++)
                s += g_spart1[((size_t)p * B_TOT + b) * CO + tid];
        } else {
#pragma unroll
            for (int p = 0; p < NCH_R; p++)
                s += g_spart2[0][((size_t)p * B_TOT + b) * CO + tid];
        }
        float n = s * s;
#pragma unroll
        for (int off = 8; off >= 1; off >>= 1)
            n += __shfl_xor_sync(0xffffffffu, n, off);
        float scale = (n / (1.f + n)) * rsqrtf(n + 1e-8f);
        float val = scale * s;
        float nb = __shfl_down_sync(0xffffffffu, val, 1);
        if (!(tid & 1)) vsh[tid >> 1] = __floats2half2_rn(val, nb);
    }
    __syncthreads();

    // wait for bulk copy (phase 0)
    asm volatile(
        "{\n\t.reg .pred P;\n\t"
        "W_%=: mbarrier.try_wait.parity.shared.b64 P, [%0], 0;\n\t"
        "@!P bra W_%=;\n\t}"
        :: "r"(mb_s) : "memory");

    // Phase A: agreement via HFMA2 + b update + softmax. 2 threads/row.
    const unsigned mask = __ballot_sync(0xffffffffu, tid < 2 * RCHK);
    if (tid < 2 * RCHK) {
        const int row = tid >> 1;
        const int c0  = (tid & 1) * 5;
        const int r   = chk * RCHK + row;
        const float* bin = (iter == 2) ? (binit + ((size_t)b * R_TOT + r) * C_N)
                                       : (g_b2  + ((size_t)b * R_TOT + r) * C_N);
        float bv[5];
#pragma unroll
        for (int j = 0; j < 5; j++) {
            const int cc = c0 + j;
            const uint4* up = reinterpret_cast<const uint4*>(uh + row * PAD_H + cc * O_N);
            uint4 qa = up[0], qb = up[1];
            const uint4* vp = reinterpret_cast<const uint4*>(vsh + cc * 8);
            uint4 va = vp[0], vb = vp[1];
            __half2 acc = __hmul2(u2h(qa.x), u2h(va.x));
            acc = __hfma2(u2h(qa.y), u2h(va.y), acc);
            acc = __hfma2(u2h(qa.z), u2h(va.z), acc);
            acc = __hfma2(u2h(qa.w), u2h(va.w), acc);
            acc = __hfma2(u2h(qb.x), u2h(vb.x), acc);
            acc = __hfma2(u2h(qb.y), u2h(vb.y), acc);
            acc = __hfma2(u2h(qb.z), u2h(vb.z), acc);
            acc = __hfma2(u2h(qb.w), u2h(vb.w), acc);
            float2 fa = __half22float2(acc);
            bv[j] = bin[cc] + fa.x + fa.y;
        }
        if (iter == 2) {  // persist b2 for iteration 3
            float* bo = g_b2 + ((size_t)b * R_TOT + r) * C_N;
#pragma unroll
            for (int j = 0; j < 5; j++) bo[c0 + j] = bv[j];
        }
        float m = bv[0];
#pragma unroll
        for (int j = 1; j < 5; j++) m = fmaxf(m, bv[j]);
        m = fmaxf(m, __shfl_xor_sync(mask, m, 1));
        float e[5], ps = 0.f;
#pragma unroll
        for (int j = 0; j < 5; j++) { e[j] = __expf(bv[j] - m); ps += e[j]; }
        ps += __shfl_xor_sync(mask, ps, 1);
        const float inv = 1.f / ps;
#pragma unroll
        for (int j = 0; j < 5; j++) cT[(c0 + j) * RCHK + row] = e[j] * inv;
    }
    __syncthreads();

    // Phase B: s partial (fp32); thread = (col pair u, row half g).
    {
        const int g = tid / 80;
        const int u = tid - g * 80;
        const int cc = u >> 3;                 // capsule of the pair
        const float4* crow = reinterpret_cast<const float4*>(cT + cc * RCHK + g * 36);
        const __half2* ucol = reinterpret_cast<const __half2*>(
            uh + (size_t)g * 36 * PAD_H) + u;
        float2 acc = make_float2(0.f, 0.f);
#pragma unroll
        for (int r4 = 0; r4 < 9; r4++) {
            float4 cf = crow[r4];
            float2 f;
            f = __half22float2(ucol[(r4 * 4 + 0) * (PAD_H / 2)]);
            acc.x = fmaf(cf.x, f.x, acc.x); acc.y = fmaf(cf.x, f.y, acc.y);
            f = __half22float2(ucol[(r4 * 4 + 1) * (PAD_H / 2)]);
            acc.x = fmaf(cf.y, f.x, acc.x); acc.y = fmaf(cf.y, f.y, acc.y);
            f = __half22float2(ucol[(r4 * 4 + 2) * (PAD_H / 2)]);
            acc.x = fmaf(cf.z, f.x, acc.x); acc.y = fmaf(cf.z, f.y, acc.y);
            f = __half22float2(ucol[(r4 * 4 + 3) * (PAD_H / 2)]);
            acc.x = fmaf(cf.w, f.x, acc.x); acc.y = fmaf(cf.w, f.y, acc.y);
        }
        reinterpret_cast<float2*>(sp + g * CO)[u] = acc;
    }
    __syncthreads();
    if (tid < CO) {
        const int slot = (iter == 2) ? 0 : 1;
        g_spart2[slot][((size_t)chk * B_TOT + b) * CO + tid] = sp[tid] + sp[CO + tid];
    }

    // Iter 3: last block per batch performs the final squash -> out.
    if (iter == 3) {
        __threadfence();
        __syncthreads();
        if (tid == 0) {
            int prev = atomicAdd(&g_cnt[b], 1);
            is_last = (prev == NCH_R - 1);
        }
        __syncthreads();
        if (is_last) {
            __threadfence();
            if (tid < CO) {
                float s = 0.f;
#pragma unroll
                for (int p = 0; p < NCH_R; p++)
                    s += g_spart2[1][((size_t)p * B_TOT + b) * CO + tid];
                float n = s * s;
#pragma unroll
                for (int off = 8; off >= 1; off >>= 1)
                    n += __shfl_xor_sync(0xffffffffu, n, off);
                float scale = (n / (1.f + n)) * rsqrtf(n + 1e-8f);
                out[(size_t)b * CO + tid] = scale * s;
            }
            if (tid == 0) g_cnt[b] = 0;   // reset for next graph replay
        }
    }
}

// ---------------------------------------------------------------------------
extern "C" void kernel_launch(void* const* d_in, const int* in_sizes, int n_in,
                              void* d_out, int out_size) {
    const float *x = nullptr, *W = nullptr, *binit = nullptr;
    for (int i = 0; i < n_in; i++) {
        if (in_sizes[i] == B_TOT * R_TOT * I_N)          x     = (const float*)d_in[i];
        else if (in_sizes[i] == R_TOT * C_N * O_N * I_N) W     = (const float*)d_in[i];
        else if (in_sizes[i] == B_TOT * R_TOT * C_N)     binit = (const float*)d_in[i];
    }
    float* out = (float*)d_out;

    const int SMEM_ROUTE = TILE_BYTES +
        (C_N * RCHK) * (int)sizeof(float) + 80 * 4 + 2 * CO * (int)sizeof(float);
    cudaFuncSetAttribute(kroute, cudaFuncAttributeMaxDynamicSharedMemorySize, SMEM_ROUTE);

    // pack W into fp16 column pairs
    k0<<<(R_TOT * 80 * I_N + 255) / 256, 256>>>(W);
    // process batches in 2 halves: each half's 49.5MB u_hat slab stays L2-resident
    // between its producer (k1) and both consumers (kroute x2).
    for (int h = 0; h < 2; h++) {
        k1<<<512, 160>>>(x, binit, h);
        kroute<<<2048, 160, SMEM_ROUTE>>>(binit, out, 2, h);
        kroute<<<2048, 160, SMEM_ROUTE>>>(binit, out, 3, h);
    }
}

// round 17
// speedup vs baseline: 1.1989x; 1.1989x over previous
#include <cuda_runtime.h>
#include <cuda_fp16.h>
#include <cstdint>

#define R_TOT 1152
#define B_TOT 256
#define B_HALF 128
#define C_N 10
#define O_N 16
#define CO 160
#define I_N 8

// kroute tiling
#define NCH_R 16           // route chunks per batch
#define RCHK 72            // rows per route chunk
#define PAD_H 168          // fp16 row stride: 336B rows, 16B-aligned
#define TILE_H (RCHK * PAD_H)          // 12096 halves
#define TILE_BYTES (TILE_H * 2)        // 24192 (16B multiple)

// k1 tiling
#define TB 8               // batches per k1 block
#define K1_RC 36           // rows per k1 block
#define K1_PARTS 32        // s1 partial chunks

// Scratch (device globals: allocation-free kernel_launch)
__device__ __half g_uh[(size_t)B_TOT * NCH_R * TILE_H];      // fp16 u_hat tiles
__device__ __half2 g_wh[(size_t)R_TOT * 80 * I_N];           // W packed column pairs
__device__ float  g_b2[(size_t)B_TOT * R_TOT * C_N];         // b after iter-1 update
__device__ float  g_spart1[(size_t)K1_PARTS * B_TOT * CO];   // k1 partial s
__device__ float  g_spart2[2][(size_t)NCH_R * B_TOT * CO];   // kroute partial s
__device__ int    g_cnt[B_TOT];                              // last-block counters

__device__ __forceinline__ uint32_t smem_u32(const void* p) {
    uint32_t a;
    asm("{ .reg .u64 t; cvta.to.shared.u64 t, %1; cvt.u32.u64 %0, t; }" : "=r"(a) : "l"(p));
    return a;
}
__device__ __forceinline__ __half2 u2h(uint32_t v) {
    return *reinterpret_cast<__half2*>(&v);
}

// ---------------------------------------------------------------------------
// K0: pack W (fp32 [R, CO, I]) into column-pair half2 layout [r][u][i].
// ---------------------------------------------------------------------------
__global__ __launch_bounds__(256) void k0(const float* __restrict__ W) {
    int idx = blockIdx.x * 256 + threadIdx.x;        // over R_TOT*80*8
    if (idx >= R_TOT * 80 * I_N) return;
    int i = idx & 7;
    int t = idx >> 3;
    int u = t % 80;
    int r = t / 80;
    float w0 = W[((size_t)r * CO + 2 * u) * I_N + i];
    float w1 = W[((size_t)r * CO + 2 * u + 1) * I_N + i];
    g_wh[idx] = __floats2half2_rn(w0, w1);
}

// ---------------------------------------------------------------------------
// K1 (per batch half): u_hat via HFMA2 (2 columns/thread) -> fp16 tiles,
// fused softmax(b_init) + fp32 s1 partials.
// grid = 16 b-tiles x 32 r-chunks = 512 blocks, 160 threads, ~21KB SMEM.
// ---------------------------------------------------------------------------
__global__ __launch_bounds__(160) void k1(const float* __restrict__ x,
                                          const float* __restrict__ binit,
                                          int b_half) {
    const int bt = blockIdx.x & 15;
    const int rc = blockIdx.x >> 4;          // 0..31 (36-row chunk)
    const int b0 = b_half * B_HALF + bt * TB;
    const int tid = threadIdx.x;
    const int r0 = rc * K1_RC;
    const int chk_g = rc >> 1;               // 72-row tile id
    const int rin0 = (rc & 1) * K1_RC;       // row offset within tile

    const int grp = tid / 80;                // batch group (4 batches each)
    const int u   = tid - grp * 80;          // column pair (cols 2u, 2u+1)
    const int c   = u >> 3;                  // capsule (same for both cols)
    const int bb0 = grp * 4;

    __shared__ __half2 x2_sm[TB][K1_RC][I_N];   // 9.2KB
    __shared__ float   c_sm[TB][K1_RC][C_N];    // 11.5KB

    const float4* x4 = reinterpret_cast<const float4*>(x);

    // stage x as duplicated half2
    for (int i = tid; i < TB * K1_RC * 2; i += 160) {
        int bb = i / (K1_RC * 2);
        int rem = i - bb * (K1_RC * 2);
        float4 v = x4[((size_t)(b0 + bb) * R_TOT + r0) * 2 + rem];
        __half2* dst = &x2_sm[bb][0][0] + rem * 4;
        dst[0] = __float2half2_rn(v.x);
        dst[1] = __float2half2_rn(v.y);
        dst[2] = __float2half2_rn(v.z);
        dst[3] = __float2half2_rn(v.w);
    }
    // softmax(b_init)
    for (int p = tid; p < TB * K1_RC; p += 160) {
        int bb = p / K1_RC;
        int rr = p - bb * K1_RC;
        const float* bp = binit + ((size_t)(b0 + bb) * R_TOT + r0 + rr) * C_N;
        float e[C_N];
        float m = bp[0];
#pragma unroll
        for (int j = 1; j < C_N; j++) m = fmaxf(m, bp[j]);
        float sum = 0.f;
#pragma unroll
        for (int j = 0; j < C_N; j++) { e[j] = __expf(bp[j] - m); sum += e[j]; }
        float inv = 1.f / sum;
#pragma unroll
        for (int j = 0; j < C_N; j++) c_sm[bb][rr][j] = e[j] * inv;
    }
    __syncthreads();

    float2 s_acc[4];
#pragma unroll
    for (int i = 0; i < 4; i++) s_acc[i] = make_float2(0.f, 0.f);

    for (int rr = 0; rr < K1_RC; rr++) {
        const int r = r0 + rr;
        const int rin = rin0 + rr;
        __half2 w[8];
        {
            const uint4* wp = reinterpret_cast<const uint4*>(g_wh + ((size_t)r * 80 + u) * I_N);
            uint4 a = wp[0], bq = wp[1];
            w[0] = u2h(a.x);  w[1] = u2h(a.y);  w[2] = u2h(a.z);  w[3] = u2h(a.w);
            w[4] = u2h(bq.x); w[5] = u2h(bq.y); w[6] = u2h(bq.z); w[7] = u2h(bq.w);
        }
#pragma unroll
        for (int bbl = 0; bbl < 4; bbl++) {
            const int bb = bb0 + bbl;
            const uint4* xq = reinterpret_cast<const uint4*>(&x2_sm[bb][rr][0]);
            uint4 xa = xq[0], xb = xq[1];
            __half2 acc = __hmul2(w[0], u2h(xa.x));
            acc = __hfma2(w[1], u2h(xa.y), acc);
            acc = __hfma2(w[2], u2h(xa.z), acc);
            acc = __hfma2(w[3], u2h(xa.w), acc);
            acc = __hfma2(w[4], u2h(xb.x), acc);
            acc = __hfma2(w[5], u2h(xb.y), acc);
            acc = __hfma2(w[6], u2h(xb.z), acc);
            acc = __hfma2(w[7], u2h(xb.w), acc);
            __half2* dst = reinterpret_cast<__half2*>(
                g_uh + ((size_t)(b0 + bb) * NCH_R + chk_g) * TILE_H + (size_t)rin * PAD_H);
            dst[u] = acc;
            float2 f = __half22float2(acc);
            const float cf = c_sm[bb][rr][c];
            s_acc[bbl].x = fmaf(cf, f.x, s_acc[bbl].x);
            s_acc[bbl].y = fmaf(cf, f.y, s_acc[bbl].y);
        }
    }
#pragma unroll
    for (int bbl = 0; bbl < 4; bbl++) {
        float2* sp = reinterpret_cast<float2*>(
            g_spart1 + ((size_t)rc * B_TOT + (b0 + bb0 + bbl)) * CO);
        sp[u] = s_acc[bbl];
    }
}

// ---------------------------------------------------------------------------
// Fused routing pass (iter = 2 or 3) over one batch half.
// Bulk-copy 24.2KB fp16 tile, overlap with v recompute (half2), phase A =
// HFMA2 agreement, phase B = fp32 accumulation.
// Iter 3 last block per batch does final squash. grid = 2048, 160 threads.
// ---------------------------------------------------------------------------
__global__ __launch_bounds__(160) void kroute(const float* __restrict__ binit,
                                              float* __restrict__ out, int iter,
                                              int b_half) {
    extern __shared__ __align__(16) char smem_raw[];
    __half* uh = reinterpret_cast<__half*>(smem_raw);             // TILE_H halves
    float* cT  = reinterpret_cast<float*>(smem_raw + TILE_BYTES); // [C_N][RCHK]
    __half2* vsh = reinterpret_cast<__half2*>(cT + C_N * RCHK);   // 80 half2
    float* sp  = reinterpret_cast<float*>(vsh + 80);              // [2][CO]
    __shared__ __align__(8) unsigned long long mbar;
    __shared__ int is_last;

    const int b   = b_half * B_HALF + (blockIdx.x >> 4);
    const int chk = blockIdx.x & 15;
    const int tid = threadIdx.x;

    const uint32_t uh_s = smem_u32(uh);
    const uint32_t mb_s = smem_u32(&mbar);

    if (tid == 0) {
        asm volatile("mbarrier.init.shared.b64 [%0], 1;" :: "r"(mb_s) : "memory");
        asm volatile("mbarrier.arrive.expect_tx.shared.b64 _, [%0], %1;"
                     :: "r"(mb_s), "r"((uint32_t)TILE_BYTES) : "memory");
        const __half* src = g_uh + ((size_t)b * NCH_R + chk) * TILE_H;
        asm volatile("cp.async.bulk.shared::cta.global.mbarrier::complete_tx::bytes "
                     "[%0], [%1], %2, [%3];"
                     :: "r"(uh_s), "l"(src), "r"((uint32_t)TILE_BYTES), "r"(mb_s)
                     : "memory");
    }

    // Overlap with bulk copy: recompute v = squash(sum of prev partials) as half2.
    if (tid < CO) {
        float s = 0.f;
        if (iter == 2) {
#pragma unroll
            for (int p = 0; p < K1_PARTS; p++)
                s += g_spart1[((size_t)p * B_TOT + b) * CO + tid];
        } else {
#pragma unroll
            for (int p = 0; p < NCH_R; p++)
                s += g_spart2[0][((size_t)p * B_TOT + b) * CO + tid];
        }
        float n = s * s;
#pragma unroll
        for (int off = 8; off >= 1; off >>= 1)
            n += __shfl_xor_sync(0xffffffffu, n, off);
        float scale = (n / (1.f + n)) * rsqrtf(n + 1e-8f);
        float val = scale * s;
        float nb = __shfl_down_sync(0xffffffffu, val, 1);
        if (!(tid & 1)) vsh[tid >> 1] = __floats2half2_rn(val, nb);
    }
    __syncthreads();

    // wait for bulk copy (phase 0)
    asm volatile(
        "{\n\t.reg .pred P;\n\t"
        "W_%=: mbarrier.try_wait.parity.shared.b64 P, [%0], 0;\n\t"
        "@!P bra W_%=;\n\t}"
        :: "r"(mb_s) : "memory");

    // Phase A: agreement via HFMA2 + b update + softmax. 2 threads/row.
    const unsigned mask = __ballot_sync(0xffffffffu, tid < 2 * RCHK);
    if (tid < 2 * RCHK) {
        const int row = tid >> 1;
        const int c0  = (tid & 1) * 5;
        const int r   = chk * RCHK + row;
        const float* bin = (iter == 2) ? (binit + ((size_t)b * R_TOT + r) * C_N)
                                       : (g_b2  + ((size_t)b * R_TOT + r) * C_N);
        float bv[5];
#pragma unroll
        for (int j = 0; j < 5; j++) {
            const int cc = c0 + j;
            const uint4* up = reinterpret_cast<const uint4*>(uh + row * PAD_H + cc * O_N);
            uint4 qa = up[0], qb = up[1];
            const uint4* vp = reinterpret_cast<const uint4*>(vsh + cc * 8);
            uint4 va = vp[0], vb = vp[1];
            __half2 acc = __hmul2(u2h(qa.x), u2h(va.x));
            acc = __hfma2(u2h(qa.y), u2h(va.y), acc);
            acc = __hfma2(u2h(qa.z), u2h(va.z), acc);
            acc = __hfma2(u2h(qa.w), u2h(va.w), acc);
            acc = __hfma2(u2h(qb.x), u2h(vb.x), acc);
            acc = __hfma2(u2h(qb.y), u2h(vb.y), acc);
            acc = __hfma2(u2h(qb.z), u2h(vb.z), acc);
            acc = __hfma2(u2h(qb.w), u2h(vb.w), acc);
            float2 fa = __half22float2(acc);
            bv[j] = bin[cc] + fa.x + fa.y;
        }
        if (iter == 2) {  // persist b2 for iteration 3
            float* bo = g_b2 + ((size_t)b * R_TOT + r) * C_N;
#pragma unroll
            for (int j = 0; j < 5; j++) bo[c0 + j] = bv[j];
        }
        float m = bv[0];
#pragma unroll
        for (int j = 1; j < 5; j++) m = fmaxf(m, bv[j]);
        m = fmaxf(m, __shfl_xor_sync(mask, m, 1));
        float e[5], ps = 0.f;
#pragma unroll
        for (int j = 0; j < 5; j++) { e[j] = __expf(bv[j] - m); ps += e[j]; }
        ps += __shfl_xor_sync(mask, ps, 1);
        const float inv = 1.f / ps;
#pragma unroll
        for (int j = 0; j < 5; j++) cT[(c0 + j) * RCHK + row] = e[j] * inv;
    }
    __syncthreads();

    // Phase B: s partial (fp32); thread = (col pair u, row half g).
    {
        const int g = tid / 80;
        const int u = tid - g * 80;
        const int cc = u >> 3;                 // capsule of the pair
        const float4* crow = reinterpret_cast<const float4*>(cT + cc * RCHK + g * 36);
        const __half2* ucol = reinterpret_cast<const __half2*>(
            uh + (size_t)g * 36 * PAD_H) + u;
        float2 acc = make_float2(0.f, 0.f);
#pragma unroll
        for (int r4 = 0; r4 < 9; r4++) {
            float4 cf = crow[r4];
            float2 f;
            f = __half22float2(ucol[(r4 * 4 + 0) * (PAD_H / 2)]);
            acc.x = fmaf(cf.x, f.x, acc.x); acc.y = fmaf(cf.x, f.y, acc.y);
            f = __half22float2(ucol[(r4 * 4 + 1) * (PAD_H / 2)]);
            acc.x = fmaf(cf.y, f.x, acc.x); acc.y = fmaf(cf.y, f.y, acc.y);
            f = __half22float2(ucol[(r4 * 4 + 2) * (PAD_H / 2)]);
            acc.x = fmaf(cf.z, f.x, acc.x); acc.y = fmaf(cf.z, f.y, acc.y);
            f = __half22float2(ucol[(r4 * 4 + 3) * (PAD_H / 2)]);
            acc.x = fmaf(cf.w, f.x, acc.x); acc.y = fmaf(cf.w, f.y, acc.y);
        }
        reinterpret_cast<float2*>(sp + g * CO)[u] = acc;
    }
    __syncthreads();
    if (tid < CO) {
        const int slot = (iter == 2) ? 0 : 1;
        g_spart2[slot][((size_t)chk * B_TOT + b) * CO + tid] = sp[tid] + sp[CO + tid];
    }

    // Iter 3: last block per batch performs the final squash -> out.
    if (iter == 3) {
        __threadfence();
        __syncthreads();
        if (tid == 0) {
            int prev = atomicAdd(&g_cnt[b], 1);
            is_last = (prev == NCH_R - 1);
        }
        __syncthreads();
        if (is_last) {
            __threadfence();
            if (tid < CO) {
                float s = 0.f;
#pragma unroll
                for (int p = 0; p < NCH_R; p++)
                    s += g_spart2[1][((size_t)p * B_TOT + b) * CO + tid];
                float n = s * s;
#pragma unroll
                for (int off = 8; off >= 1; off >>= 1)
                    n += __shfl_xor_sync(0xffffffffu, n, off);
                float scale = (n / (1.f + n)) * rsqrtf(n + 1e-8f);
                out[(size_t)b * CO + tid] = scale * s;
            }
            if (tid == 0) g_cnt[b] = 0;   // reset for next graph replay
        }
    }
}

// ---------------------------------------------------------------------------
// Two independent per-half pipelines on two streams, forked/joined with
// events on the capture (default) stream. Halves touch disjoint state
// (everything indexed by b), so the chains are race-free.
// ---------------------------------------------------------------------------
extern "C" void kernel_launch(void* const* d_in, const int* in_sizes, int n_in,
                              void* d_out, int out_size) {
    const float *x = nullptr, *W = nullptr, *binit = nullptr;
    for (int i = 0; i < n_in; i++) {
        if (in_sizes[i] == B_TOT * R_TOT * I_N)          x     = (const float*)d_in[i];
        else if (in_sizes[i] == R_TOT * C_N * O_N * I_N) W     = (const float*)d_in[i];
        else if (in_sizes[i] == B_TOT * R_TOT * C_N)     binit = (const float*)d_in[i];
    }
    float* out = (float*)d_out;

    const int SMEM_ROUTE = TILE_BYTES +
        (C_N * RCHK) * (int)sizeof(float) + 80 * 4 + 2 * CO * (int)sizeof(float);
    cudaFuncSetAttribute(kroute, cudaFuncAttributeMaxDynamicSharedMemorySize, SMEM_ROUTE);

    // one-time resources (handles only; no device memory). Work per call is
    // identical on every invocation.
    static cudaStream_t s1 = nullptr, s2 = nullptr;
    static cudaEvent_t evf = nullptr, ej1 = nullptr, ej2 = nullptr;
    if (s1 == nullptr) {
        cudaStreamCreateWithFlags(&s1, cudaStreamNonBlocking);
        cudaStreamCreateWithFlags(&s2, cudaStreamNonBlocking);
        cudaEventCreateWithFlags(&evf, cudaEventDisableTiming);
        cudaEventCreateWithFlags(&ej1, cudaEventDisableTiming);
        cudaEventCreateWithFlags(&ej2, cudaEventDisableTiming);
    }

    // pack W on the main stream, then fork
    k0<<<(R_TOT * 80 * I_N + 255) / 256, 256>>>(W);
    cudaEventRecord(evf, 0);
    cudaStreamWaitEvent(s1, evf, 0);
    cudaStreamWaitEvent(s2, evf, 0);

    // half 0 chain
    k1<<<512, 160, 0, s1>>>(x, binit, 0);
    kroute<<<2048, 160, SMEM_ROUTE, s1>>>(binit, out, 2, 0);
    kroute<<<2048, 160, SMEM_ROUTE, s1>>>(binit, out, 3, 0);
    // half 1 chain (fully independent)
    k1<<<512, 160, 0, s2>>>(x, binit, 1);
    kroute<<<2048, 160, SMEM_ROUTE, s2>>>(binit, out, 2, 1);
    kroute<<<2048, 160, SMEM_ROUTE, s2>>>(binit, out, 3, 1);

    // join back onto the main (capture) stream
    cudaEventRecord(ej1, s1);
    cudaEventRecord(ej2, s2);
    cudaStreamWaitEvent(0, ej1, 0);
    cudaStreamWaitEvent(0, ej2, 0);
}